// round 11
// baseline (speedup 1.0000x reference)
#include <cuda_runtime.h>

// diff_pred: 16-tap LPC FIR with mu-law decode/encode.
//   sig: (2048, 2400, 1) fp32   lpc: (2048, 15, 16) fp32   out: (2048, 2400, 1) fp32
//
// 16 outputs/thread, register FIR, smem halo exchange. Registers capped at 64
// (4 blocks/SM) by splitting the FIR into two 8-tap passes so only 8
// coefficients are live at a time.

#define NTAPS     16
#define T_LEN     2400
#define NFRAMES   15
#define OPT       16
#define SEGS      (T_LEN / OPT)    // 150 segments per row
#define SLOT      20               // padded smem floats per thread

__device__ __forceinline__ float ex2_fast(float a) {
    float r;
    asm("ex2.approx.ftz.f32 %0, %1;" : "=f"(r) : "f"(a));
    return r;
}

// mu-law decode: u2l(raw) = copysign(SINV*(2^(|raw-128|/16) - 1), raw-128)
__device__ __forceinline__ float u2l_fast(float raw) {
    const float SINV = 32768.0f / 255.0f;
    float t = fmaf(raw, 0.0625f, -8.0f);       // sign/16x-scaled |raw-128|
    float e = ex2_fast(fabsf(t));
    float m = fmaf(SINV, e, -SINV);
    return copysignf(m, t);
}

__global__ __launch_bounds__(256, 4)
void diff_pred_79336635892364_kernel(const float* __restrict__ sig,
                                     const float* __restrict__ lpc,
                                     float* __restrict__ out)
{
    __shared__ float xs[256 * SLOT];

    const float SC = 255.0f / 32768.0f;

    const int tid   = threadIdx.x;
    const int g     = blockIdx.x * blockDim.x + tid;
    const int batch = g / SEGS;
    const int seg   = g - batch * SEGS;
    const int t0    = seg * OPT;

    const float* __restrict__ srow = sig + (size_t)batch * T_LEN;
    const float* __restrict__ crow =
        lpc + ((size_t)batch * NFRAMES + seg / (160 / OPT)) * NTAPS;

    // ---- load + decode own 16 samples, publish to smem ----
    float xw[2 * NTAPS];
    {
        float raw[OPT];
        const float4* sp = reinterpret_cast<const float4*>(srow + t0);
        float4* rv = reinterpret_cast<float4*>(raw);
        #pragma unroll
        for (int i = 0; i < 4; i++) rv[i] = sp[i];
        #pragma unroll
        for (int k = 0; k < OPT; k++) xw[NTAPS + k] = u2l_fast(raw[k]);
    }
    {
        float4* slot = reinterpret_cast<float4*>(xs + tid * SLOT);
        const float4* ov = reinterpret_cast<const float4*>(&xw[NTAPS]);
        #pragma unroll
        for (int i = 0; i < 4; i++) slot[i] = ov[i];
    }
    __syncthreads();

    // ---- halo xw[0..15] = decoded previous segment ----
    if (seg == 0) {
        #pragma unroll
        for (int k = 0; k < NTAPS; k++) xw[k] = 0.0f;   // u2l(128) == 0
    } else if (tid == 0) {
        const float4* sp = reinterpret_cast<const float4*>(srow + t0 - NTAPS);
        float hraw[NTAPS];
        float4* hv = reinterpret_cast<float4*>(hraw);
        #pragma unroll
        for (int i = 0; i < 4; i++) hv[i] = sp[i];
        #pragma unroll
        for (int k = 0; k < NTAPS; k++) xw[k] = u2l_fast(hraw[k]);
    } else {
        const float4* hs = reinterpret_cast<const float4*>(xs + (tid - 1) * SLOT);
        float4* hv = reinterpret_cast<float4*>(xw);
        #pragma unroll
        for (int i = 0; i < 4; i++) hv[i] = hs[i];
    }

    // ---- 16x16 FIR in two 8-tap passes (only 8 coeffs live at a time) ----
    float acc[OPT];
    {
        float c[8];
        {
            const float4* lp = reinterpret_cast<const float4*>(crow);
            float4* cv = reinterpret_cast<float4*>(c);
            cv[0] = lp[0]; cv[1] = lp[1];
        }
        #pragma unroll
        for (int i = 0; i < OPT; i++) acc[i] = c[0] * xw[NTAPS + i];
        #pragma unroll
        for (int j = 1; j < 8; j++) {
            #pragma unroll
            for (int i = 0; i < OPT; i++)
                acc[i] = fmaf(c[j], xw[NTAPS + i - j], acc[i]);
        }
        {
            const float4* lp = reinterpret_cast<const float4*>(crow + 8);
            float4* cv = reinterpret_cast<float4*>(c);
            cv[0] = lp[0]; cv[1] = lp[1];
        }
        #pragma unroll
        for (int j = 8; j < NTAPS; j++) {
            #pragma unroll
            for (int i = 0; i < OPT; i++)
                acc[i] = fmaf(c[j - 8], xw[NTAPS + i - j], acc[i]);
        }
    }

    // ---- mu-law encode: r = clip(fma(copysign(16,-a), log2(1+SC*|a|), 128), 0, 255)
    #pragma unroll
    for (int i = 0; i < OPT; i++) {
        float a   = acc[i];
        float v   = __log2f(fmaf(SC, fabsf(a), 1.0f));   // >= 0
        float s16 = copysignf(16.0f, -a);
        float r   = fmaf(s16, v, 128.0f);
        acc[i]    = fminf(fmaxf(r, 0.0f), 255.0f);
    }

    // ---- vector store ----
    float4* ovp = reinterpret_cast<float4*>(out + (size_t)batch * T_LEN + t0);
    const float4* rr = reinterpret_cast<const float4*>(acc);
    #pragma unroll
    for (int i = 0; i < 4; i++) ovp[i] = rr[i];
}

extern "C" void kernel_launch(void* const* d_in, const int* in_sizes, int n_in,
                              void* d_out, int out_size)
{
    const float* sig = (const float*)d_in[0];
    const float* lpc = (const float*)d_in[1];
    float* out = (float*)d_out;

    const int batches = in_sizes[0] / T_LEN;          // 2048
    const int total_threads = batches * SEGS;         // 307200
    dim3 block(256);
    dim3 grid((total_threads + 255) / 256);           // 1200
    diff_pred_79336635892364_kernel<<<grid, block>>>(sig, lpc, out);
}

// round 13
// speedup vs baseline: 1.1170x; 1.1170x over previous
#include <cuda_runtime.h>

// diff_pred: 16-tap LPC FIR with mu-law decode/encode.
//   sig: (2048, 2400, 1) fp32   lpc: (2048, 15, 16) fp32   out: (2048, 2400, 1) fp32
//
// 8 outputs/thread (fine grain to shrink the last-wave tail), 5 blocks/SM via
// 51-reg cap. Each thread decodes its own 8 samples, publishes to padded smem,
// and pulls its 16-tap halo from the two previous threads' slots. Register FIR
// in two 8-tap passes.

#define NTAPS     16
#define T_LEN     2400
#define NFRAMES   15
#define OPT       8
#define SEGS      (T_LEN / OPT)    // 300 segments per row
#define SLOT      12               // floats per smem slot (conflict-free stride)

__device__ __forceinline__ float ex2_fast(float a) {
    float r;
    asm("ex2.approx.ftz.f32 %0, %1;" : "=f"(r) : "f"(a));
    return r;
}

// mu-law decode: u2l(raw) = copysign(SINV*(2^(|raw-128|/16) - 1), raw-128)
__device__ __forceinline__ float u2l_fast(float raw) {
    const float SINV = 32768.0f / 255.0f;
    float t = fmaf(raw, 0.0625f, -8.0f);       // sign & 16x-scaled |raw-128|
    float e = ex2_fast(fabsf(t));
    float m = fmaf(SINV, e, -SINV);
    return copysignf(m, t);
}

__global__ __launch_bounds__(256, 5)
void diff_pred_79336635892364_kernel(const float* __restrict__ sig,
                                     const float* __restrict__ lpc,
                                     float* __restrict__ out)
{
    __shared__ float xs[256 * SLOT];

    const float SC = 255.0f / 32768.0f;

    const int tid   = threadIdx.x;
    const int g     = blockIdx.x * 256 + tid;
    const int batch = g / SEGS;
    const int seg   = g - batch * SEGS;
    const int t0    = seg * OPT;

    const float* __restrict__ srow = sig + (size_t)batch * T_LEN;

    // x[0..15] = halo (previous 16 decoded samples), x[16..23] = own outputs' inputs
    float x[NTAPS + OPT];

    // ---- load + decode own 8 samples ----
    {
        float raw[OPT];
        const float4* sp = reinterpret_cast<const float4*>(srow + t0);
        reinterpret_cast<float4*>(raw)[0] = sp[0];
        reinterpret_cast<float4*>(raw)[1] = sp[1];
        #pragma unroll
        for (int k = 0; k < OPT; k++) x[NTAPS + k] = u2l_fast(raw[k]);
    }
    // ---- publish to smem slot ----
    {
        float4* slot = reinterpret_cast<float4*>(xs + tid * SLOT);
        slot[0] = reinterpret_cast<const float4*>(&x[NTAPS])[0];
        slot[1] = reinterpret_cast<const float4*>(&x[NTAPS])[1];
    }
    __syncthreads();

    // ---- halo: x[8..15] = seg-1 outputs, x[0..7] = seg-2 outputs ----
    if (seg == 0) {
        #pragma unroll
        for (int k = 0; k < NTAPS; k++) x[k] = 0.0f;     // u2l(128) == 0
    } else {
        if (tid >= 1) {
            const float4* hs = reinterpret_cast<const float4*>(xs + (tid - 1) * SLOT);
            reinterpret_cast<float4*>(&x[8])[0] = hs[0];
            reinterpret_cast<float4*>(&x[8])[1] = hs[1];
        } else {
            float hr[8];
            const float4* sp = reinterpret_cast<const float4*>(srow + t0 - 8);
            reinterpret_cast<float4*>(hr)[0] = sp[0];
            reinterpret_cast<float4*>(hr)[1] = sp[1];
            #pragma unroll
            for (int k = 0; k < 8; k++) x[8 + k] = u2l_fast(hr[k]);
        }
        if (seg == 1) {
            #pragma unroll
            for (int k = 0; k < 8; k++) x[k] = 0.0f;
        } else if (tid >= 2) {
            const float4* hs = reinterpret_cast<const float4*>(xs + (tid - 2) * SLOT);
            reinterpret_cast<float4*>(&x[0])[0] = hs[0];
            reinterpret_cast<float4*>(&x[0])[1] = hs[1];
        } else {
            float hr[8];
            const float4* sp = reinterpret_cast<const float4*>(srow + t0 - 16);
            reinterpret_cast<float4*>(hr)[0] = sp[0];
            reinterpret_cast<float4*>(hr)[1] = sp[1];
            #pragma unroll
            for (int k = 0; k < 8; k++) x[k] = u2l_fast(hr[k]);
        }
    }

    // ---- 16-tap FIR over 8 outputs, two 8-tap passes (8 coeffs live) ----
    const float* __restrict__ crow =
        lpc + ((size_t)batch * NFRAMES + seg / (160 / OPT)) * NTAPS;
    float acc[OPT];
    {
        float c[8];
        {
            const float4* lp = reinterpret_cast<const float4*>(crow);
            reinterpret_cast<float4*>(c)[0] = lp[0];
            reinterpret_cast<float4*>(c)[1] = lp[1];
        }
        #pragma unroll
        for (int i = 0; i < OPT; i++) acc[i] = c[0] * x[NTAPS + i];
        #pragma unroll
        for (int j = 1; j < 8; j++) {
            #pragma unroll
            for (int i = 0; i < OPT; i++)
                acc[i] = fmaf(c[j], x[NTAPS + i - j], acc[i]);
        }
        {
            const float4* lp = reinterpret_cast<const float4*>(crow + 8);
            reinterpret_cast<float4*>(c)[0] = lp[0];
            reinterpret_cast<float4*>(c)[1] = lp[1];
        }
        #pragma unroll
        for (int j = 8; j < NTAPS; j++) {
            #pragma unroll
            for (int i = 0; i < OPT; i++)
                acc[i] = fmaf(c[j - 8], x[NTAPS + i - j], acc[i]);
        }
    }

    // ---- mu-law encode: clip(fma(copysign(16,-a), log2(1+SC*|a|), 128), 0, 255)
    #pragma unroll
    for (int i = 0; i < OPT; i++) {
        float a = acc[i];
        float v = __log2f(fmaf(SC, fabsf(a), 1.0f));    // >= 0
        float r = fmaf(copysignf(16.0f, -a), v, 128.0f);
        acc[i]  = fminf(fmaxf(r, 0.0f), 255.0f);
    }

    // ---- vector store ----
    float4* ov = reinterpret_cast<float4*>(out + (size_t)batch * T_LEN + t0);
    ov[0] = reinterpret_cast<const float4*>(acc)[0];
    ov[1] = reinterpret_cast<const float4*>(acc)[1];
}

extern "C" void kernel_launch(void* const* d_in, const int* in_sizes, int n_in,
                              void* d_out, int out_size)
{
    const float* sig = (const float*)d_in[0];
    const float* lpc = (const float*)d_in[1];
    float* out = (float*)d_out;

    const int batches = in_sizes[0] / T_LEN;          // 2048
    const int total_threads = batches * SEGS;         // 614400
    dim3 block(256);
    dim3 grid((total_threads + 255) / 256);           // 2400
    diff_pred_79336635892364_kernel<<<grid, block>>>(sig, lpc, out);
}